// round 8
// baseline (speedup 1.0000x reference)
#include <cuda_runtime.h>
#include <cuda_bf16.h>
#include <cstdint>

// Problem constants (fixed: N=131072, C=1024, D=128)
#define NROWS 131072
#define CROWS 1024
#define DDIM  128

#define BM 128
#define BN 128
#define NT 8                  // M-tiles per CTA (1024 y-tiles / 128 grid.y)
// smem: B tile 32KB + A double buffer 2x32KB
#define TILE_BYTES 32768
#define SMEM_NEED (3 * TILE_BYTES)

// ---------------------------------------------------------------------------
// Device scratch (no cudaMalloc allowed)
// ---------------------------------------------------------------------------
__device__ float g_xsq[NROWS];
__device__ float g_wsq[CROWS];
__device__ __nv_bfloat16 g_xb[(size_t)NROWS * DDIM];  // bf16(x)
__device__ __nv_bfloat16 g_wb[(size_t)CROWS * DDIM];

// ---------------------------------------------------------------------------
// PTX helpers — base-target-safe only (NO tcgen05: harness targets plain sm_103)
// ---------------------------------------------------------------------------
__device__ __forceinline__ uint32_t smem_u32(const void* p) {
    uint32_t a;
    asm("{ .reg .u64 t; cvta.to.shared.u64 t, %1; cvt.u32.u64 %0, t; }"
        : "=r"(a) : "l"(p));
    return a;
}

__device__ __forceinline__ void cp_async16(uint32_t dst, const void* src) {
    asm volatile("cp.async.cg.shared.global [%0], [%1], 16;"
                 :: "r"(dst), "l"(src));
}
#define CP_COMMIT()  asm volatile("cp.async.commit_group;" ::: "memory")
#define CP_WAIT0()   asm volatile("cp.async.wait_group 0;" ::: "memory")

__device__ __forceinline__ void ldsm_x4(uint32_t& r0, uint32_t& r1,
                                        uint32_t& r2, uint32_t& r3, uint32_t a) {
    asm volatile("ldmatrix.sync.aligned.m8n8.x4.shared.b16 {%0,%1,%2,%3}, [%4];"
                 : "=r"(r0), "=r"(r1), "=r"(r2), "=r"(r3) : "r"(a));
}

__device__ __forceinline__ void mma16816(float* c, const uint32_t* a,
                                         const uint32_t* b) {
    asm volatile(
        "mma.sync.aligned.m16n8k16.row.col.f32.bf16.bf16.f32 "
        "{%0,%1,%2,%3}, {%4,%5,%6,%7}, {%8,%9}, {%0,%1,%2,%3};"
        : "+f"(c[0]), "+f"(c[1]), "+f"(c[2]), "+f"(c[3])
        : "r"(a[0]), "r"(a[1]), "r"(a[2]), "r"(a[3]), "r"(b[0]), "r"(b[1]));
}

__device__ __forceinline__ void stcs_f2(float* p, float2 v) {
    asm volatile("st.global.cs.v2.f32 [%0], {%1,%2};" :: "l"(p), "f"(v.x), "f"(v.y)
                 : "memory");
}

// 256B-pitch row swizzle: 16B unit u (0..15) XOR (row & 7) -> conflict-free
// ldmatrix phases and cp.async stores.
__device__ __forceinline__ uint32_t tile_off(int row, int u) {
    return (uint32_t)(row * 256 + ((u ^ (row & 7)) << 4));
}

// ---------------------------------------------------------------------------
// Kernel 1: fp32 -> bf16 conversion + exact fp32 row norms. One warp per row.
// ---------------------------------------------------------------------------
__global__ __launch_bounds__(256)
void convert_kernel(const float* __restrict__ x, const float* __restrict__ w) {
    const int gwarp = (blockIdx.x * blockDim.x + threadIdx.x) >> 5;
    const int lane  = threadIdx.x & 31;
    if (gwarp >= NROWS + CROWS) return;

    const bool isx = gwarp < NROWS;
    const int r = isx ? gwarp : gwarp - NROWS;
    const float* base = isx ? (x + (size_t)r * DDIM) : (w + (size_t)r * DDIM);

    float4 v = reinterpret_cast<const float4*>(base)[lane];
    float f[4] = {v.x, v.y, v.z, v.w};

    float s = f[0]*f[0] + f[1]*f[1] + f[2]*f[2] + f[3]*f[3];
    #pragma unroll
    for (int o = 16; o > 0; o >>= 1)
        s += __shfl_xor_sync(0xffffffffu, s, o);

    uint32_t hb[4];
    #pragma unroll
    for (int i = 0; i < 4; i++)
        hb[i] = (uint32_t)__bfloat16_as_ushort(__float2bfloat16_rn(f[i]));
    uint2 H;
    H.x = hb[0] | (hb[1] << 16); H.y = hb[2] | (hb[3] << 16);

    __nv_bfloat16* dst = isx ? (g_xb + (size_t)r * DDIM) : (g_wb + (size_t)r * DDIM);
    reinterpret_cast<uint2*>(dst)[lane] = H;

    if (lane == 0) {
        if (isx) g_xsq[r] = s; else g_wsq[r] = s;
    }
}

// ---------------------------------------------------------------------------
// Kernel 2: multi-tile pipelined bf16 GEMM (mma.sync) + fused distance epilogue.
// Each CTA: fixed 128-col B tile (loaded once), loops over NT=8 M-tiles with
// double-buffered A; cp.async for tile t+1 overlaps MMA + streaming stores of t.
// ---------------------------------------------------------------------------
__global__ __launch_bounds__(256, 2)
void mma_dist_kernel(float* __restrict__ out) {
    extern __shared__ char sdyn[];
    const uint32_t Bb  = smem_u32(sdyn);
    const uint32_t Ab0 = Bb + TILE_BYTES;          // A buffers: Ab0, Ab0+TILE_BYTES

    const int tid    = threadIdx.x;
    const int lane   = tid & 31;
    const int wid    = tid >> 5;
    const int warp_m = wid & 1;
    const int warp_n = wid >> 1;
    const int bn     = blockIdx.x * BN;            // prototype tile (8)
    const int bm0    = blockIdx.y * (NT * BM);     // first x tile for this CTA

    // per-thread load decomposition: 2048 16B units/tile, 8 per thread
    const int ld_r = (tid * 8) >> 4;               // 4 consecutive rows? no:
    // c = tid + i*256 -> r = c>>4, u = c&15 (thread covers same u pattern)
    uint32_t ld_off[8];
    uint32_t ld_src[8];                            // element offset within a tile
    #pragma unroll
    for (int i = 0; i < 8; i++) {
        const int c = tid + i * 256;
        const int r = c >> 4, u = c & 15;
        ld_off[i] = tile_off(r, u);
        ld_src[i] = (uint32_t)(r * DDIM + u * 8);
    }
    (void)ld_r;

    // ---- Prologue: load B tile + A tile 0 (one commit group) ----
    {
        const __nv_bfloat16* srcB = g_wb + (size_t)bn * DDIM;
        const __nv_bfloat16* srcA = g_xb + (size_t)bm0 * DDIM;
        #pragma unroll
        for (int i = 0; i < 8; i++) {
            cp_async16(Bb  + ld_off[i], srcB + ld_src[i]);
            cp_async16(Ab0 + ld_off[i], srcA + ld_src[i]);
        }
        CP_COMMIT();
    }

    // ldmatrix lane-address components
    const int a_row = warp_m * 64 + (lane & 15);            // + mi*16
    const int a_u0  = lane >> 4;                            // + ks*2
    const int b_row = warp_n * 32 + (lane & 7) + ((lane >> 4) << 3);  // + nj*16
    const int b_u0  = (lane >> 3) & 1;                      // + ks*2

    // wsq for this CTA's column strip (constant across tiles)
    const int ec = (lane & 3) * 2;
    const int er = lane >> 2;
    float ws[4][2];
    #pragma unroll
    for (int ni = 0; ni < 4; ni++) {
        const int n = bn + warp_n * 32 + ni * 8 + ec;
        ws[ni][0] = g_wsq[n];
        ws[ni][1] = g_wsq[n + 1];
    }

    for (int t = 0; t < NT; t++) {
        const int bm = bm0 + t * BM;
        const uint32_t Acur = Ab0 + (uint32_t)(t & 1) * TILE_BYTES;

        CP_WAIT0();           // A[t] (and B at t=0) resident
        __syncthreads();      // all warps past tile t-1 compute -> other buffer free

        if (t + 1 < NT) {     // prefetch A[t+1] under this tile's compute/stores
            const uint32_t Anext = Ab0 + (uint32_t)((t + 1) & 1) * TILE_BYTES;
            const __nv_bfloat16* srcA = g_xb + (size_t)(bm + BM) * DDIM;
            #pragma unroll
            for (int i = 0; i < 8; i++)
                cp_async16(Anext + ld_off[i], srcA + ld_src[i]);
            CP_COMMIT();
        }

        float acc[4][4][4];
        #pragma unroll
        for (int mi = 0; mi < 4; mi++)
            #pragma unroll
            for (int ni = 0; ni < 4; ni++)
                #pragma unroll
                for (int q = 0; q < 4; q++)
                    acc[mi][ni][q] = 0.0f;

        #pragma unroll
        for (int ks = 0; ks < 8; ks++) {
            uint32_t a[4][4], b[4][2];
            #pragma unroll
            for (int mi = 0; mi < 4; mi++)
                ldsm_x4(a[mi][0], a[mi][1], a[mi][2], a[mi][3],
                        Acur + tile_off(a_row + mi * 16, a_u0 + ks * 2));
            #pragma unroll
            for (int nj = 0; nj < 2; nj++)   // x4 -> fragments for ni=2*nj, 2*nj+1
                ldsm_x4(b[2*nj][0], b[2*nj][1], b[2*nj+1][0], b[2*nj+1][1],
                        Bb + tile_off(b_row + nj * 16, b_u0 + ks * 2));
            #pragma unroll
            for (int mi = 0; mi < 4; mi++)
                #pragma unroll
                for (int ni = 0; ni < 4; ni++)
                    mma16816(acc[mi][ni], a[mi], b[ni]);
        }

        // ---- Epilogue: dist = xsq + wsq - 2*acc (streaming stores) ----
        #pragma unroll
        for (int mi = 0; mi < 4; mi++) {
            const int r0 = bm + warp_m * 64 + mi * 16 + er;
            const int r1 = r0 + 8;
            const float xs0 = g_xsq[r0];
            const float xs1 = g_xsq[r1];
            float* row0 = out + (size_t)r0 * CROWS + bn + warp_n * 32 + ec;
            float* row1 = out + (size_t)r1 * CROWS + bn + warp_n * 32 + ec;
            #pragma unroll
            for (int ni = 0; ni < 4; ni++) {
                float2 o0, o1;
                o0.x = fmaf(-2.0f, acc[mi][ni][0], xs0 + ws[ni][0]);
                o0.y = fmaf(-2.0f, acc[mi][ni][1], xs0 + ws[ni][1]);
                o1.x = fmaf(-2.0f, acc[mi][ni][2], xs1 + ws[ni][0]);
                o1.y = fmaf(-2.0f, acc[mi][ni][3], xs1 + ws[ni][1]);
                stcs_f2(row0 + ni * 8, o0);
                stcs_f2(row1 + ni * 8, o1);
            }
        }
    }
}

// ---------------------------------------------------------------------------
extern "C" void kernel_launch(void* const* d_in, const int* in_sizes, int n_in,
                              void* d_out, int out_size) {
    const float* x = (const float*)d_in[0];   // [N, D]
    const float* w = (const float*)d_in[1];   // [C, D]
    float* out = (float*)d_out;               // [N, C]

    static bool attr_set = false;
    if (!attr_set) {
        cudaFuncSetAttribute(mma_dist_kernel,
                             cudaFuncAttributeMaxDynamicSharedMemorySize, SMEM_NEED);
        attr_set = true;
    }

    // 1) bf16 conversion + norms (warp per row)
    const int total_rows = NROWS + CROWS;
    const int blocks = (total_rows * 32 + 255) / 256;
    convert_kernel<<<blocks, 256>>>(x, w);

    // 2) pipelined tensor-core distance GEMM
    dim3 grid(CROWS / BN, NROWS / (BM * NT));  // (8, 128)
    mma_dist_kernel<<<grid, 256, SMEM_NEED>>>(out);
}